// round 2
// baseline (speedup 1.0000x reference)
#include <cuda_runtime.h>
#include <math.h>

typedef unsigned long long ull;

// Problem dims
#define BB 64
#define NN 133
#define NROW (BB*NN)
#define F0 75
#define F1 150
#define H1 256
#define H2 128

// ---------------- scratch ----------------
__device__ float g_bufA[(size_t)NROW * 256];
__device__ float g_bufB[(size_t)NROW * 256];

__device__ int   g_nz_cnt[NROW];
__device__ int   g_nz_idx[(size_t)NROW * NN];
__device__ float g_nz_val[(size_t)NROW * NN];
__device__ int   g_pl_cnt[NROW];
__device__ int   g_pl_idx[(size_t)NROW * NN];

// ---------------- f32x2 helpers ----------------
__device__ __forceinline__ ull pk2(float x, float y) {
    ull r;
    asm("mov.b64 %0, {%1, %2};" : "=l"(r) : "f"(x), "f"(y));
    return r;
}
__device__ __forceinline__ void upk2(ull v, float& x, float& y) {
    asm("mov.b64 {%0, %1}, %2;" : "=f"(x), "=f"(y) : "l"(v));
}
#define FMA2(acc, a, b) asm("fma.rn.f32x2 %0, %1, %2, %0;" : "+l"(acc) : "l"(a), "l"(b))

// ---------------- build sparse lists from adj (warp per row) ----------------
__global__ void k_build_lists(const float* __restrict__ adj) {
    int warp_in_blk = threadIdx.x >> 5;
    int lane = threadIdx.x & 31;
    int wg = blockIdx.x * (blockDim.x >> 5) + warp_in_blk;
    if (wg >= NROW) return;
    const float* arow = adj + (size_t)wg * NN;

    int cnz = 0, cpl = 0;
    unsigned lt = (1u << lane) - 1u;
    for (int base = 0; base < NN; base += 32) {
        int j = base + lane;
        float a = (j < NN) ? arow[j] : 0.0f;
        bool nz = (j < NN) && (a != 0.0f);
        bool pl = (j < NN) && (a > 1e-5f);
        unsigned mnz = __ballot_sync(0xffffffffu, nz);
        unsigned mpl = __ballot_sync(0xffffffffu, pl);
        if (nz) {
            int pos = cnz + __popc(mnz & lt);
            g_nz_idx[(size_t)wg * NN + pos] = j;
            g_nz_val[(size_t)wg * NN + pos] = a;
        }
        if (pl) {
            int pos = cpl + __popc(mpl & lt);
            g_pl_idx[(size_t)wg * NN + pos] = j;
        }
        cnz += __popc(mnz);
        cpl += __popc(mpl);
    }
    if (lane == 0) { g_nz_cnt[wg] = cnz; g_pl_cnt[wg] = cpl; }
}

// ---------------- dense GEMM with packed f32x2 over row pairs ----------------
// 20 rows per block; sAT[k][20] transposed tile; each thread owns NC cols
// (g = t + c*blockDim). 10 FFMA2 per col per k (20 rows).
template<int NC>
__global__ void k_dense_v(const float* __restrict__ A, const float* __restrict__ W,
                          const float* __restrict__ bias, float* __restrict__ Cc,
                          int K, int G, int do_relu) {
    int b  = blockIdx.y;
    int r0 = blockIdx.x * 20;
    extern __shared__ float sAT[];         // [K][20]
    int tot = K * 20;
    for (int idx = threadIdx.x; idx < tot; idx += blockDim.x) {
        int r = idx / K, k = idx - r * K;  // coalesced global read
        int row = r0 + r;
        sAT[k * 20 + r] = (row < NN) ? A[(size_t)(b * NN + row) * K + k] : 0.0f;
    }
    __syncthreads();

    int t = threadIdx.x;
    if (t >= G) return;
    int nt = blockDim.x;

    ull acc[NC][10];
    #pragma unroll
    for (int c = 0; c < NC; c++)
        #pragma unroll
        for (int p = 0; p < 10; p++) acc[c][p] = 0ull;

    #pragma unroll 2
    for (int k = 0; k < K; k++) {
        const ull* ap = reinterpret_cast<const ull*>(sAT + k * 20);
        ull a2[10];
        #pragma unroll
        for (int p = 0; p < 10; p++) a2[p] = ap[p];   // broadcast LDS.64
        #pragma unroll
        for (int c = 0; c < NC; c++) {
            int g = t + c * nt;
            float w = (g < G) ? W[(size_t)k * G + g] : 0.0f;
            ull w2 = pk2(w, w);
            #pragma unroll
            for (int p = 0; p < 10; p++) FMA2(acc[c][p], a2[p], w2);
        }
    }

    #pragma unroll
    for (int c = 0; c < NC; c++) {
        int g = t + c * nt;
        if (g >= G) continue;
        float bv = bias ? bias[g] : 0.0f;
        #pragma unroll
        for (int p = 0; p < 10; p++) {
            float v0, v1;
            upk2(acc[c][p], v0, v1);
            v0 += bv; v1 += bv;
            if (do_relu) { v0 = fmaxf(v0, 0.0f); v1 = fmaxf(v1, 0.0f); }
            int row0 = r0 + 2 * p, row1 = row0 + 1;
            if (row0 < NN) Cc[(size_t)(b * NN + row0) * G + g] = v0;
            if (row1 < NN) Cc[(size_t)(b * NN + row1) * G + g] = v1;
        }
    }
}

// ---------------- fused spmm + relu + pool (64-col chunk per block) -------
// grid (ceil(G/64), B), block 256. sT, sH in smem.
__global__ void k_spmm_pool(const float* __restrict__ T, const float* __restrict__ bias,
                            float* __restrict__ P, int G) {
    int b  = blockIdx.y;
    int cb = blockIdx.x << 6;
    extern __shared__ float sm[];
    float* sT = sm;             // [133][64]
    float* sH = sm + NN * 64;   // [133][64]

    for (int idx = threadIdx.x; idx < NN * 64; idx += blockDim.x) {
        int r = idx >> 6, c = idx & 63;
        int col = cb + c;
        sT[idx] = (col < G) ? T[(size_t)(b * NN + r) * G + col] : 0.0f;
    }
    __syncthreads();

    int cp = threadIdx.x & 31;      // col pair
    int c0 = cp * 2;
    int col0 = cb + c0, col1 = col0 + 1;
    int rg = threadIdx.x >> 5;      // 0..7, row stride 8 (warp-uniform row)
    float b0 = (col0 < G) ? bias[col0] : 0.0f;
    float b1 = (col1 < G) ? bias[col1] : 0.0f;

    for (int r = rg; r < NN; r += 8) {
        int row = b * NN + r;
        int cnt = g_nz_cnt[row];
        const int*   ji = g_nz_idx + (size_t)row * NN;
        const float* vv = g_nz_val + (size_t)row * NN;
        ull acc = pk2(b0, b1);
        for (int e = 0; e < cnt; e++) {
            int j = ji[e];
            float v = vv[e];
            ull t2 = *reinterpret_cast<const ull*>(sT + j * 64 + c0);
            FMA2(acc, t2, pk2(v, v));
        }
        float h0, h1;
        upk2(acc, h0, h1);
        sH[r * 64 + c0]     = fmaxf(h0, 0.0f);
        sH[r * 64 + c0 + 1] = fmaxf(h1, 0.0f);
    }
    __syncthreads();

    for (int r = rg; r < NN; r += 8) {
        int row = b * NN + r;
        int cnt = g_pl_cnt[row];
        const int* ji = g_pl_idx + (size_t)row * NN;
        float m0 = 0.0f, m1 = 0.0f;   // relu'd values >= 0, so 0-init == -inf+where
        for (int e = 0; e < cnt; e++) {
            int j = ji[e];
            m0 = fmaxf(m0, sH[j * 64 + c0]);
            m1 = fmaxf(m1, sH[j * 64 + c0 + 1]);
        }
        if (col0 < G) P[(size_t)row * G + col0] = m0;
        if (col1 < G) P[(size_t)row * G + col1] = m1;
    }
}

// ---------------- fused tail: gc3 spmm+relu, pool, gc4, fc1, fin, sigmoid --
// One block per batch; whole 133x75 tile lives in smem.
__global__ void k_last(const float* __restrict__ T3, const float* __restrict__ gc3_b,
                       const float* __restrict__ gc4_w, const float* __restrict__ gc4_b,
                       const float* __restrict__ fc1_w, const float* __restrict__ fc1_b,
                       const float* __restrict__ fin_w, const float* __restrict__ fin_b,
                       float* __restrict__ out) {
    int b = blockIdx.x;
    int t = threadIdx.x;
    extern __shared__ float sm[];
    float* sT = sm;             // [133][76]  (T3, later reused for P3)
    float* sH = sm + NN * 76;   // [133][76]  (Hout3)
    __shared__ float t4[NN];
    __shared__ float hh[NN];
    __shared__ float rr[3];

    for (int idx = t; idx < NN * F0; idx += blockDim.x) {
        int r = idx / F0, k = idx - r * F0;
        sT[r * 76 + k] = T3[(size_t)(b * NN + r) * F0 + k];
    }
    __syncthreads();

    int col = t % 76;
    int rg  = t / 76;           // 0..2 active (t < 228)
    bool cok = (t < 228) && (col < F0);

    // spmm + relu  (Hout3)
    if (t < 228) {
        float bv = cok ? gc3_b[col] : 0.0f;
        for (int r = rg; r < NN; r += 3) {
            int row = b * NN + r;
            int cnt = g_nz_cnt[row];
            const int*   ji = g_nz_idx + (size_t)row * NN;
            const float* vv = g_nz_val + (size_t)row * NN;
            float acc = bv;
            for (int e = 0; e < cnt; e++)
                acc = fmaf(vv[e], sT[ji[e] * 76 + col], acc);
            sH[r * 76 + col] = fmaxf(acc, 0.0f);
        }
    }
    __syncthreads();

    // pool -> P3 (overwrite sT)
    if (t < 228) {
        for (int r = rg; r < NN; r += 3) {
            int row = b * NN + r;
            int cnt = g_pl_cnt[row];
            const int* ji = g_pl_idx + (size_t)row * NN;
            float m = 0.0f;
            for (int e = 0; e < cnt; e++)
                m = fmaxf(m, sH[ji[e] * 76 + col]);
            sT[r * 76 + col] = m;
        }
    }
    __syncthreads();

    // t4 = P3 @ gc4_w
    if (t < NN) {
        float a = 0.0f;
        #pragma unroll
        for (int k = 0; k < F0; k++) a = fmaf(sT[t * 76 + k], gc4_w[k], a);
        t4[t] = a;
    }
    __syncthreads();

    // hh = relu(adj . t4 + gc4_b)
    if (t < NN) {
        int row = b * NN + t;
        int cnt = g_nz_cnt[row];
        const int*   ji = g_nz_idx + (size_t)row * NN;
        const float* vv = g_nz_val + (size_t)row * NN;
        float acc = gc4_b[0];
        for (int e = 0; e < cnt; e++)
            acc = fmaf(vv[e], t4[ji[e]], acc);
        hh[t] = fmaxf(acc, 0.0f);
    }
    __syncthreads();

    if (t < 3) {
        float a = fc1_b[t];
        for (int k = 0; k < NN - 1; k++)
            a = fmaf(hh[k + 1], fc1_w[k * 3 + t], a);
        rr[t] = a;
    }
    __syncthreads();

    if (t == 0) {
        float z = hh[0] * fin_w[0] + rr[0] * fin_w[1] + rr[1] * fin_w[2]
                + rr[2] * fin_w[3] + fin_b[0];
        out[b] = 1.0f / (1.0f + expf(-z));
    }
}

// ---------------- launch ----------------
extern "C" void kernel_launch(void* const* d_in, const int* in_sizes, int n_in,
                              void* d_out, int out_size) {
    const float* x     = (const float*)d_in[0];
    const float* adj   = (const float*)d_in[1];
    const float* emb_w = (const float*)d_in[2];
    const float* emb_b = (const float*)d_in[3];
    const float* gc1_w = (const float*)d_in[4];
    const float* gc1_b = (const float*)d_in[5];
    const float* gc2_w = (const float*)d_in[6];
    const float* gc2_b = (const float*)d_in[7];
    const float* gc3_w = (const float*)d_in[8];
    const float* gc3_b = (const float*)d_in[9];
    const float* gc4_w = (const float*)d_in[10];
    const float* gc4_b = (const float*)d_in[11];
    const float* fc1_w = (const float*)d_in[12];
    const float* fc1_b = (const float*)d_in[13];
    const float* fin_w = (const float*)d_in[14];
    const float* fin_b = (const float*)d_in[15];
    float* out = (float*)d_out;

    float *dA, *dB;
    cudaGetSymbolAddress((void**)&dA, g_bufA);
    cudaGetSymbolAddress((void**)&dB, g_bufB);

    cudaFuncSetAttribute(k_spmm_pool, cudaFuncAttributeMaxDynamicSharedMemorySize, 70000);
    cudaFuncSetAttribute(k_last,      cudaFuncAttributeMaxDynamicSharedMemorySize, 84000);

    // 0) sparse lists
    {
        int warps_per_blk = 8;
        int blocks = (NROW + warps_per_blk - 1) / warps_per_blk;
        k_build_lists<<<blocks, warps_per_blk * 32>>>(adj);
    }

    dim3 gdense(7, BB);     // 7 * 20 rows >= 133

    // 1) emb: dA = relu(x @ emb_w + emb_b)     [.,150]
    k_dense_v<2><<<gdense, 96, 75 * 20 * sizeof(float)>>>(x, emb_w, emb_b, dA, F0, F1, 1);
    // 2) dB = dA @ gc1_w                       [.,256]
    k_dense_v<2><<<gdense, 128, 150 * 20 * sizeof(float)>>>(dA, gc1_w, nullptr, dB, F1, H1, 0);
    // 3) dA = pool(relu(adj.dB + gc1_b))       [.,256]
    k_spmm_pool<<<dim3(4, BB), 256, 2 * NN * 64 * sizeof(float)>>>(dB, gc1_b, dA, H1);
    // 4) dB = dA @ gc2_w                       [.,128]
    k_dense_v<1><<<gdense, 128, 256 * 20 * sizeof(float)>>>(dA, gc2_w, nullptr, dB, H1, H2, 0);
    // 5) dA = pool(relu(adj.dB + gc2_b))       [.,128]
    k_spmm_pool<<<dim3(2, BB), 256, 2 * NN * 64 * sizeof(float)>>>(dB, gc2_b, dA, H2);
    // 6) dB = dA @ gc3_w                       [.,75]
    k_dense_v<1><<<gdense, 96, 128 * 20 * sizeof(float)>>>(dA, gc3_w, nullptr, dB, H2, F0, 0);
    // 7) fused tail
    k_last<<<BB, 256, 2 * NN * 76 * sizeof(float)>>>(dB, gc3_b, gc4_w, gc4_b,
                                                     fc1_w, fc1_b, fin_w, fin_b, out);
}

// round 3
// speedup vs baseline: 1.1378x; 1.1378x over previous
#include <cuda_runtime.h>
#include <math.h>

typedef unsigned long long ull;

// Problem dims
#define BB 64
#define NN 133
#define NROW (BB*NN)
#define F0 75
#define F1 150
#define H1 256
#define H2 128

// ---------------- scratch ----------------
__device__ float g_bufA[(size_t)NROW * 256];
__device__ float g_bufB[(size_t)NROW * 256];

__device__ int   g_nz_cnt[NROW];
__device__ ull   g_nz[(size_t)NROW * NN];      // packed {val:hi32, idx:lo32}
__device__ int   g_pl_cnt[NROW];
__device__ int   g_pl_idx[(size_t)NROW * NN];

// ---------------- f32x2 helpers ----------------
__device__ __forceinline__ ull pk2(float x, float y) {
    ull r;
    asm("mov.b64 %0, {%1, %2};" : "=l"(r) : "f"(x), "f"(y));
    return r;
}
__device__ __forceinline__ void upk2(ull v, float& x, float& y) {
    asm("mov.b64 {%0, %1}, %2;" : "=f"(x), "=f"(y) : "l"(v));
}
#define FMA2(acc, a, b) asm("fma.rn.f32x2 %0, %1, %2, %0;" : "+l"(acc) : "l"(a), "l"(b))

// ---------------- build sparse lists from adj (warp per row) ----------------
__global__ void k_build_lists(const float* __restrict__ adj) {
    int warp_in_blk = threadIdx.x >> 5;
    int lane = threadIdx.x & 31;
    int wg = blockIdx.x * (blockDim.x >> 5) + warp_in_blk;
    if (wg >= NROW) return;
    const float* arow = adj + (size_t)wg * NN;

    int cnz = 0, cpl = 0;
    unsigned lt = (1u << lane) - 1u;
    for (int base = 0; base < NN; base += 32) {
        int j = base + lane;
        float a = (j < NN) ? arow[j] : 0.0f;
        bool nz = (j < NN) && (a != 0.0f);
        bool pl = (j < NN) && (a > 1e-5f);
        unsigned mnz = __ballot_sync(0xffffffffu, nz);
        unsigned mpl = __ballot_sync(0xffffffffu, pl);
        if (nz) {
            int pos = cnz + __popc(mnz & lt);
            g_nz[(size_t)wg * NN + pos] =
                ((ull)__float_as_uint(a) << 32) | (unsigned)j;
        }
        if (pl) {
            int pos = cpl + __popc(mpl & lt);
            g_pl_idx[(size_t)wg * NN + pos] = j;
        }
        cnz += __popc(mnz);
        cpl += __popc(mpl);
    }
    if (lane == 0) { g_nz_cnt[wg] = cnz; g_pl_cnt[wg] = cpl; }
}

// ---------------- dense GEMM with packed f32x2 over row pairs ----------------
// 20 rows per block; sAT[k][20] transposed tile; each thread owns NC cols.
template<int NC>
__global__ void k_dense_v(const float* __restrict__ A, const float* __restrict__ W,
                          const float* __restrict__ bias, float* __restrict__ Cc,
                          int K, int G, int do_relu) {
    int b  = blockIdx.y;
    int r0 = blockIdx.x * 20;
    extern __shared__ float sAT[];         // [K][20]
    int tot = K * 20;
    for (int idx = threadIdx.x; idx < tot; idx += blockDim.x) {
        int r = idx / K, k = idx - r * K;  // coalesced global read
        int row = r0 + r;
        sAT[k * 20 + r] = (row < NN) ? A[(size_t)(b * NN + row) * K + k] : 0.0f;
    }
    __syncthreads();

    int t = threadIdx.x;
    if (t >= G) return;
    int nt = blockDim.x;

    ull acc[NC][10];
    #pragma unroll
    for (int c = 0; c < NC; c++)
        #pragma unroll
        for (int p = 0; p < 10; p++) acc[c][p] = 0ull;

    #pragma unroll 2
    for (int k = 0; k < K; k++) {
        const ull* ap = reinterpret_cast<const ull*>(sAT + k * 20);
        ull a2[10];
        #pragma unroll
        for (int p = 0; p < 10; p++) a2[p] = ap[p];   // broadcast LDS.64
        #pragma unroll
        for (int c = 0; c < NC; c++) {
            int g = t + c * nt;
            float w = (g < G) ? W[(size_t)k * G + g] : 0.0f;
            ull w2 = pk2(w, w);
            #pragma unroll
            for (int p = 0; p < 10; p++) FMA2(acc[c][p], a2[p], w2);
        }
    }

    #pragma unroll
    for (int c = 0; c < NC; c++) {
        int g = t + c * nt;
        if (g >= G) continue;
        float bv = bias ? bias[g] : 0.0f;
        #pragma unroll
        for (int p = 0; p < 10; p++) {
            float v0, v1;
            upk2(acc[c][p], v0, v1);
            v0 += bv; v1 += bv;
            if (do_relu) { v0 = fmaxf(v0, 0.0f); v1 = fmaxf(v1, 0.0f); }
            int row0 = r0 + 2 * p, row1 = row0 + 1;
            if (row0 < NN) Cc[(size_t)(b * NN + row0) * G + g] = v0;
            if (row1 < NN) Cc[(size_t)(b * NN + row1) * G + g] = v1;
        }
    }
}

// ---------------- spmm + relu, 2 cols/thread (f32x2) ----------------
// grid (ceil(NN/RPB), BB), block (G/2, RPB). G even.
__global__ void k_spmm2(const float* __restrict__ T, const float* __restrict__ bias,
                        float* __restrict__ O, int G) {
    int b = blockIdx.y;
    int i = blockIdx.x * blockDim.y + threadIdx.y;
    if (i >= NN) return;
    int row = b * NN + i;
    int g0 = threadIdx.x * 2;

    int cnt = g_nz_cnt[row];
    const ull* L = g_nz + (size_t)row * NN;
    const float* Tb = T + (size_t)b * NN * G + g0;

    ull acc = pk2(bias[g0], bias[g0 + 1]);
    int e = 0;
    for (; e + 2 <= cnt; e += 2) {
        ull p0 = L[e], p1 = L[e + 1];              // uniform LDG.64
        int j0 = (int)(unsigned)p0, j1 = (int)(unsigned)p1;
        float v0 = __uint_as_float((unsigned)(p0 >> 32));
        float v1 = __uint_as_float((unsigned)(p1 >> 32));
        ull t0 = *reinterpret_cast<const ull*>(Tb + (size_t)j0 * G);
        ull t1 = *reinterpret_cast<const ull*>(Tb + (size_t)j1 * G);
        FMA2(acc, t0, pk2(v0, v0));
        FMA2(acc, t1, pk2(v1, v1));
    }
    if (e < cnt) {
        ull p0 = L[e];
        int j0 = (int)(unsigned)p0;
        float v0 = __uint_as_float((unsigned)(p0 >> 32));
        ull t0 = *reinterpret_cast<const ull*>(Tb + (size_t)j0 * G);
        FMA2(acc, t0, pk2(v0, v0));
    }
    float h0, h1;
    upk2(acc, h0, h1);
    O[(size_t)row * G + g0]     = fmaxf(h0, 0.0f);
    O[(size_t)row * G + g0 + 1] = fmaxf(h1, 0.0f);
}

// ---------------- neighbor max-pool, 4 cols/thread (float4) ----------------
// grid (ceil(NN/RPB), BB), block (G/4, RPB). G % 4 == 0.
__global__ void k_pool4(const float* __restrict__ H, float* __restrict__ O, int G) {
    int b = blockIdx.y;
    int i = blockIdx.x * blockDim.y + threadIdx.y;
    if (i >= NN) return;
    int row = b * NN + i;
    int g0 = threadIdx.x * 4;

    int cnt = g_pl_cnt[row];
    const int* ji = g_pl_idx + (size_t)row * NN;
    const float4* Hb = reinterpret_cast<const float4*>(H + (size_t)b * NN * G + g0);
    int pitch = G >> 2;

    // H is post-relu (>=0); cnt==0 -> 0, so 0-init == masked -inf + where.
    float4 m = make_float4(0.f, 0.f, 0.f, 0.f);
    int e = 0;
    for (; e + 2 <= cnt; e += 2) {
        int j0 = ji[e], j1 = ji[e + 1];
        float4 h0 = Hb[(size_t)j0 * pitch];
        float4 h1 = Hb[(size_t)j1 * pitch];
        m.x = fmaxf(m.x, fmaxf(h0.x, h1.x));
        m.y = fmaxf(m.y, fmaxf(h0.y, h1.y));
        m.z = fmaxf(m.z, fmaxf(h0.z, h1.z));
        m.w = fmaxf(m.w, fmaxf(h0.w, h1.w));
    }
    if (e < cnt) {
        float4 h0 = Hb[(size_t)ji[e] * pitch];
        m.x = fmaxf(m.x, h0.x); m.y = fmaxf(m.y, h0.y);
        m.z = fmaxf(m.z, h0.z); m.w = fmaxf(m.w, h0.w);
    }
    reinterpret_cast<float4*>(O + (size_t)row * G + g0)[0] = m;
}

// ---------------- fused tail: gc3 spmm+relu, pool, gc4, fc1, fin, sigmoid --
__global__ void k_last(const float* __restrict__ T3, const float* __restrict__ gc3_b,
                       const float* __restrict__ gc4_w, const float* __restrict__ gc4_b,
                       const float* __restrict__ fc1_w, const float* __restrict__ fc1_b,
                       const float* __restrict__ fin_w, const float* __restrict__ fin_b,
                       float* __restrict__ out) {
    int b = blockIdx.x;
    int t = threadIdx.x;
    extern __shared__ float sm[];
    float* sT = sm;             // [133][76]
    float* sH = sm + NN * 76;   // [133][76]
    __shared__ float t4[NN];
    __shared__ float hh[NN];
    __shared__ float rr[3];

    for (int idx = t; idx < NN * F0; idx += blockDim.x) {
        int r = idx / F0, k = idx - r * F0;
        sT[r * 76 + k] = T3[(size_t)(b * NN + r) * F0 + k];
    }
    __syncthreads();

    int col = t % 76;
    int rg  = t / 76;
    bool cok = (t < 228) && (col < F0);

    if (t < 228) {
        float bv = cok ? gc3_b[col] : 0.0f;
        for (int r = rg; r < NN; r += 3) {
            int row = b * NN + r;
            int cnt = g_nz_cnt[row];
            const ull* L = g_nz + (size_t)row * NN;
            float acc = bv;
            for (int e = 0; e < cnt; e++) {
                ull p = L[e];
                acc = fmaf(__uint_as_float((unsigned)(p >> 32)),
                           sT[(int)(unsigned)p * 76 + col], acc);
            }
            sH[r * 76 + col] = fmaxf(acc, 0.0f);
        }
    }
    __syncthreads();

    if (t < 228) {
        for (int r = rg; r < NN; r += 3) {
            int row = b * NN + r;
            int cnt = g_pl_cnt[row];
            const int* ji = g_pl_idx + (size_t)row * NN;
            float m = 0.0f;
            for (int e = 0; e < cnt; e++)
                m = fmaxf(m, sH[ji[e] * 76 + col]);
            sT[r * 76 + col] = m;
        }
    }
    __syncthreads();

    if (t < NN) {
        float a = 0.0f;
        #pragma unroll
        for (int k = 0; k < F0; k++) a = fmaf(sT[t * 76 + k], gc4_w[k], a);
        t4[t] = a;
    }
    __syncthreads();

    if (t < NN) {
        int row = b * NN + t;
        int cnt = g_nz_cnt[row];
        const ull* L = g_nz + (size_t)row * NN;
        float acc = gc4_b[0];
        for (int e = 0; e < cnt; e++) {
            ull p = L[e];
            acc = fmaf(__uint_as_float((unsigned)(p >> 32)), t4[(int)(unsigned)p], acc);
        }
        hh[t] = fmaxf(acc, 0.0f);
    }
    __syncthreads();

    if (t < 3) {
        float a = fc1_b[t];
        for (int k = 0; k < NN - 1; k++)
            a = fmaf(hh[k + 1], fc1_w[k * 3 + t], a);
        rr[t] = a;
    }
    __syncthreads();

    if (t == 0) {
        float z = hh[0] * fin_w[0] + rr[0] * fin_w[1] + rr[1] * fin_w[2]
                + rr[2] * fin_w[3] + fin_b[0];
        out[b] = 1.0f / (1.0f + expf(-z));
    }
}

// ---------------- launch ----------------
extern "C" void kernel_launch(void* const* d_in, const int* in_sizes, int n_in,
                              void* d_out, int out_size) {
    const float* x     = (const float*)d_in[0];
    const float* adj   = (const float*)d_in[1];
    const float* emb_w = (const float*)d_in[2];
    const float* emb_b = (const float*)d_in[3];
    const float* gc1_w = (const float*)d_in[4];
    const float* gc1_b = (const float*)d_in[5];
    const float* gc2_w = (const float*)d_in[6];
    const float* gc2_b = (const float*)d_in[7];
    const float* gc3_w = (const float*)d_in[8];
    const float* gc3_b = (const float*)d_in[9];
    const float* gc4_w = (const float*)d_in[10];
    const float* gc4_b = (const float*)d_in[11];
    const float* fc1_w = (const float*)d_in[12];
    const float* fc1_b = (const float*)d_in[13];
    const float* fin_w = (const float*)d_in[14];
    const float* fin_b = (const float*)d_in[15];
    float* out = (float*)d_out;

    float *dA, *dB;
    cudaGetSymbolAddress((void**)&dA, g_bufA);
    cudaGetSymbolAddress((void**)&dB, g_bufB);

    cudaFuncSetAttribute(k_last, cudaFuncAttributeMaxDynamicSharedMemorySize, 84000);

    // 0) sparse lists
    {
        int warps_per_blk = 8;
        int blocks = (NROW + warps_per_blk - 1) / warps_per_blk;
        k_build_lists<<<blocks, warps_per_blk * 32>>>(adj);
    }

    dim3 gdense(7, BB);     // 7 * 20 rows >= 133

    // 1) emb: dA = relu(x @ emb_w + emb_b)     [.,150]
    k_dense_v<2><<<gdense, 96, 75 * 20 * sizeof(float)>>>(x, emb_w, emb_b, dA, F0, F1, 1);
    // 2) dB = dA @ gc1_w                       [.,256]
    k_dense_v<2><<<gdense, 128, 150 * 20 * sizeof(float)>>>(dA, gc1_w, nullptr, dB, F1, H1, 0);
    // 3) dA = relu(adj.dB + gc1_b)             [.,256]
    k_spmm2<<<dim3(67, BB), dim3(128, 2)>>>(dB, gc1_b, dA, H1);
    // 4) dB = pool(dA)                         [.,256]
    k_pool4<<<dim3(34, BB), dim3(64, 4)>>>(dA, dB, H1);
    // 5) dA = dB @ gc2_w                       [.,128]
    k_dense_v<1><<<gdense, 128, 256 * 20 * sizeof(float)>>>(dB, gc2_w, nullptr, dA, H1, H2, 0);
    // 6) dB = relu(adj.dA + gc2_b)             [.,128]
    k_spmm2<<<dim3(67, BB), dim3(64, 2)>>>(dA, gc2_b, dB, H2);
    // 7) dA = pool(dB)                         [.,128]
    k_pool4<<<dim3(34, BB), dim3(32, 4)>>>(dB, dA, H2);
    // 8) dB = dA @ gc3_w                       [.,75]
    k_dense_v<1><<<gdense, 96, 128 * 20 * sizeof(float)>>>(dA, gc3_w, nullptr, dB, H2, F0, 0);
    // 9) fused tail
    k_last<<<BB, 256, 2 * NN * 76 * sizeof(float)>>>(dB, gc3_b, gc4_w, gc4_b,
                                                     fc1_w, fc1_b, fin_w, fin_b, out);
}